// round 1
// baseline (speedup 1.0000x reference)
#include <cuda_runtime.h>
#include <math.h>
#include <stdint.h>

#define NN 40000
#define EE 320000

// ---------------- scratch (device globals; no allocation allowed) ----------------
__device__ float g_QKV[NN * 384];           // per-node [Q(128)|K(128)|V(128)], Q pre-scaled by 1/sqrt(32)
__device__ float g_ekv[(long long)EE * 256];// per-sorted-edge [ek(128)|ev(128)]
__device__ float g_attraw[NN * 128];
__device__ float g_pre[NN * 128];
__device__ float g_att[NN * 128];
__device__ float g_inter[NN * 512];
__device__ float g_m[NN * 128];
__device__ float g_hst[NN * 128];
__device__ float g_xst[NN * 128];
__device__ float g_gi[NN * 384];
__device__ float g_gh[NN * 384];
__device__ float g_Wqkv[128 * 384];
__device__ float g_bqkv[384];
__device__ float g_Wkve[128 * 256];
__device__ float g_Wao[128 * 128];
__device__ float g_Wint[128 * 512];
__device__ float g_Wout[512 * 128];
__device__ float g_Wih[128 * 384];
__device__ float g_Whh[128 * 384];
__device__ int   g_cnt[NN];
__device__ int   g_rowptr[NN + 1];
__device__ int   g_cur[NN];
__device__ int   g_srcs[EE];
__device__ int   g_eidxs[EE];

// ---------------- weight prep ----------------
__global__ void build_wqkv_kernel(const float* __restrict__ wq, const float* __restrict__ wk,
                                  const float* __restrict__ wv) {
    int idx = blockIdx.x * blockDim.x + threadIdx.x;
    if (idx >= 384 * 128) return;
    int n = idx / 128, k = idx % 128;
    const float SC = 0.17677669529663687f; // 1/sqrt(32)
    float v;
    if (n < 128)      v = wq[n * 128 + k] * SC;
    else if (n < 256) v = wk[(n - 128) * 128 + k];
    else              v = wv[(n - 256) * 128 + k];
    g_Wqkv[k * 384 + n] = v;
}

__global__ void build_bqkv_kernel(const float* __restrict__ bq, const float* __restrict__ bk,
                                  const float* __restrict__ bv) {
    int n = blockIdx.x * blockDim.x + threadIdx.x;
    if (n >= 384) return;
    const float SC = 0.17677669529663687f;
    float v;
    if (n < 128)      v = bq[n] * SC;
    else if (n < 256) v = bk[n - 128];
    else              v = bv[n - 256];
    g_bqkv[n] = v;
}

__global__ void build_wkve_kernel(const float* __restrict__ wk, const float* __restrict__ wv) {
    int idx = blockIdx.x * blockDim.x + threadIdx.x;
    if (idx >= 256 * 128) return;
    int n = idx / 128, k = idx % 128;
    float v = (n < 128) ? wk[n * 128 + k] : wv[(n - 128) * 128 + k];
    g_Wkve[k * 256 + n] = v;
}

// generic W[Nout,K] -> Wt[K,Nout]
__global__ void transpose_kernel(const float* __restrict__ W, float* __restrict__ Wt,
                                 int Nout, int K) {
    int idx = blockIdx.x * blockDim.x + threadIdx.x;
    if (idx >= Nout * K) return;
    int n = idx / K, k = idx % K;
    Wt[k * Nout + n] = W[idx];
}

// ---------------- CSR build ----------------
__global__ void hist_kernel(const int* __restrict__ dst) {
    int i = blockIdx.x * blockDim.x + threadIdx.x;
    if (i < EE) atomicAdd(&g_cnt[dst[i]], 1);
}

__global__ void scan_kernel() {
    __shared__ int part[1024];
    int t = threadIdx.x;
    const int per = (NN + 1023) / 1024;
    int base = t * per;
    int s = 0;
    for (int i = 0; i < per; i++) {
        int idx = base + i;
        if (idx < NN) s += g_cnt[idx];
    }
    part[t] = s;
    __syncthreads();
    if (t == 0) {
        int r = 0;
        for (int i = 0; i < 1024; i++) { int v = part[i]; part[i] = r; r += v; }
        g_rowptr[NN] = r;
    }
    __syncthreads();
    int r = part[t];
    for (int i = 0; i < per; i++) {
        int idx = base + i;
        if (idx < NN) {
            g_rowptr[idx] = r;
            g_cur[idx] = r;
            r += g_cnt[idx];
        }
    }
}

__global__ void scatter_kernel(const int* __restrict__ src, const int* __restrict__ dst) {
    int i = blockIdx.x * blockDim.x + threadIdx.x;
    if (i >= EE) return;
    int d = dst[i];
    int p = atomicAdd(&g_cur[d], 1);
    g_srcs[p] = src[i];
    g_eidxs[p] = i;
}

// ---------------- tiled fp32 GEMM: C = A @ Wt (+bias, +res, gelu) ----------------
// A: [M,K] (rows optionally gathered via rowmap), Wt: [K,Nout], C: [M,Nout]
// EPI: 0 none, 1 bias, 2 bias+residual, 3 bias+gelu(exact)
template <int EPI>
__global__ void __launch_bounds__(256) gemm_kernel(
    const float* __restrict__ A, const float* __restrict__ Wt,
    const float* __restrict__ bias, const float* __restrict__ res,
    float* __restrict__ C, int M, int Nout, int K,
    const int* __restrict__ rowmap)
{
    __shared__ float As[16][128];
    __shared__ float Bs[16][128];
    const int tid = threadIdx.x;
    const int bm = blockIdx.x * 128;
    const int bn = blockIdx.y * 128;
    const int tx = tid & 15;
    const int ty = tid >> 4;

    const int a_row = tid >> 1;
    const int a_kv  = (tid & 1) * 4;
    int ar = bm + a_row;
    if (ar >= M) ar = M - 1;
    if (rowmap) ar = rowmap[ar];
    const float* Arow = A + (size_t)ar * K;

    const int b_n = (tid & 31) * 4;
    const int b_k = tid >> 5;

    float acc[8][8];
#pragma unroll
    for (int i = 0; i < 8; i++)
#pragma unroll
        for (int j = 0; j < 8; j++) acc[i][j] = 0.f;

    for (int k0 = 0; k0 < K; k0 += 16) {
        float4 av0 = *(const float4*)(Arow + k0 + a_kv);
        float4 av1 = *(const float4*)(Arow + k0 + 8 + a_kv);
        float4 bv0 = *(const float4*)(Wt + (size_t)(k0 + b_k) * Nout + bn + b_n);
        float4 bv1 = *(const float4*)(Wt + (size_t)(k0 + b_k + 8) * Nout + bn + b_n);
        As[a_kv + 0][a_row] = av0.x; As[a_kv + 1][a_row] = av0.y;
        As[a_kv + 2][a_row] = av0.z; As[a_kv + 3][a_row] = av0.w;
        As[8 + a_kv + 0][a_row] = av1.x; As[8 + a_kv + 1][a_row] = av1.y;
        As[8 + a_kv + 2][a_row] = av1.z; As[8 + a_kv + 3][a_row] = av1.w;
        *(float4*)&Bs[b_k][b_n] = bv0;
        *(float4*)&Bs[b_k + 8][b_n] = bv1;
        __syncthreads();
#pragma unroll
        for (int kk = 0; kk < 16; kk++) {
            float a[8], b[8];
            *(float4*)&a[0] = *(const float4*)&As[kk][ty * 8];
            *(float4*)&a[4] = *(const float4*)&As[kk][ty * 8 + 4];
            *(float4*)&b[0] = *(const float4*)&Bs[kk][tx * 8];
            *(float4*)&b[4] = *(const float4*)&Bs[kk][tx * 8 + 4];
#pragma unroll
            for (int i = 0; i < 8; i++)
#pragma unroll
                for (int j = 0; j < 8; j++)
                    acc[i][j] += a[i] * b[j];
        }
        __syncthreads();
    }

#pragma unroll
    for (int i = 0; i < 8; i++) {
        int row = bm + ty * 8 + i;
        if (row >= M) continue;
        float* Crow = C + (size_t)row * Nout + bn;
        const float* Rrow = (EPI == 2) ? (res + (size_t)row * Nout + bn) : nullptr;
#pragma unroll
        for (int j = 0; j < 8; j++) {
            float v = acc[i][j];
            int col = bn + tx * 8 + j;
            if (EPI >= 1) v += bias[col];
            if (EPI == 2) v += Rrow[tx * 8 + j];
            if (EPI == 3) v = 0.5f * v * (1.f + erff(v * 0.70710678118654752f));
            Crow[tx * 8 + j] = v;
        }
    }
}

// ---------------- GAT: warp per node, online softmax over incoming edges ----------------
__global__ void gat_kernel() {
    int w = (blockIdx.x * blockDim.x + threadIdx.x) >> 5;
    int lane = threadIdx.x & 31;
    if (w >= NN) return;
    float q[4], mx[4], sm[4], acc[4];
#pragma unroll
    for (int h = 0; h < 4; h++) {
        q[h] = g_QKV[w * 384 + h * 32 + lane];
        mx[h] = -1e30f; sm[h] = 0.f; acc[h] = 0.f;
    }
    int beg = g_rowptr[w], end = g_rowptr[w + 1];
    for (int p = beg; p < end; p++) {
        int s = g_srcs[p];
        const float* kb = g_QKV + (size_t)s * 384 + 128;
        const float* eb = g_ekv + (size_t)p * 256;
        float kv[4], vv[4], d[4];
#pragma unroll
        for (int h = 0; h < 4; h++) {
            kv[h] = kb[h * 32 + lane] + eb[h * 32 + lane];
            vv[h] = kb[128 + h * 32 + lane] + eb[128 + h * 32 + lane];
            d[h] = q[h] * kv[h];
        }
#pragma unroll
        for (int off = 16; off > 0; off >>= 1)
#pragma unroll
            for (int h = 0; h < 4; h++)
                d[h] += __shfl_xor_sync(0xffffffffu, d[h], off);
#pragma unroll
        for (int h = 0; h < 4; h++) {
            float a = d[h];
            float nm = fmaxf(mx[h], a);
            float c = __expf(mx[h] - nm);
            float pe = __expf(a - nm);
            sm[h] = sm[h] * c + pe;
            acc[h] = acc[h] * c + pe * vv[h];
            mx[h] = nm;
        }
    }
#pragma unroll
    for (int h = 0; h < 4; h++)
        g_attraw[w * 128 + h * 32 + lane] = acc[h] / (sm[h] + 1e-16f);
}

// ---------------- LayerNorm: warp per row (H=128) ----------------
__global__ void ln_kernel(const float* __restrict__ in, const float* __restrict__ g,
                          const float* __restrict__ b, float* __restrict__ out) {
    int w = (blockIdx.x * blockDim.x + threadIdx.x) >> 5;
    int lane = threadIdx.x & 31;
    if (w >= NN) return;
    const float* row = in + (size_t)w * 128;
    float v[4];
    float s = 0.f;
#pragma unroll
    for (int j = 0; j < 4; j++) { v[j] = row[j * 32 + lane]; s += v[j]; }
#pragma unroll
    for (int off = 16; off > 0; off >>= 1) s += __shfl_xor_sync(0xffffffffu, s, off);
    float mean = s * (1.f / 128.f);
    float s2 = 0.f;
#pragma unroll
    for (int j = 0; j < 4; j++) { float d = v[j] - mean; s2 += d * d; }
#pragma unroll
    for (int off = 16; off > 0; off >>= 1) s2 += __shfl_xor_sync(0xffffffffu, s2, off);
    float inv = rsqrtf(s2 * (1.f / 128.f) + 1e-12f);
#pragma unroll
    for (int j = 0; j < 4; j++) {
        int e = j * 32 + lane;
        out[(size_t)w * 128 + e] = g[e] * (v[j] - mean) * inv + b[e];
    }
}

// ---------------- GRU gates + h update + LN3 -> x ----------------
__global__ void gru_ln_kernel(const float* __restrict__ lng, const float* __restrict__ lnb) {
    int w = (blockIdx.x * blockDim.x + threadIdx.x) >> 5;
    int lane = threadIdx.x & 31;
    if (w >= NN) return;
    float hn[4];
    float s = 0.f;
#pragma unroll
    for (int j = 0; j < 4; j++) {
        int e = j * 32 + lane;
        size_t b3 = (size_t)w * 384;
        float ir = g_gi[b3 + e], iz = g_gi[b3 + 128 + e], in_ = g_gi[b3 + 256 + e];
        float hr = g_gh[b3 + e], hz = g_gh[b3 + 128 + e], hnn = g_gh[b3 + 256 + e];
        float hv = g_hst[(size_t)w * 128 + e];
        float r = 1.f / (1.f + expf(-(ir + hr)));
        float z = 1.f / (1.f + expf(-(iz + hz)));
        float n = tanhf(in_ + r * hnn);
        float hnew = (1.f - z) * n + z * hv;
        g_hst[(size_t)w * 128 + e] = hnew;
        hn[j] = hnew;
        s += hnew;
    }
#pragma unroll
    for (int off = 16; off > 0; off >>= 1) s += __shfl_xor_sync(0xffffffffu, s, off);
    float mean = s * (1.f / 128.f);
    float s2 = 0.f;
#pragma unroll
    for (int j = 0; j < 4; j++) { float d = hn[j] - mean; s2 += d * d; }
#pragma unroll
    for (int off = 16; off > 0; off >>= 1) s2 += __shfl_xor_sync(0xffffffffu, s2, off);
    float inv = rsqrtf(s2 * (1.f / 128.f) + 1e-12f);
#pragma unroll
    for (int j = 0; j < 4; j++) {
        int e = j * 32 + lane;
        g_xst[(size_t)w * 128 + e] = lng[e] * (hn[j] - mean) * inv + lnb[e];
    }
}

__global__ void copy4_kernel(float4* __restrict__ dst, const float4* __restrict__ src, int n) {
    int i = blockIdx.x * blockDim.x + threadIdx.x;
    if (i < n) dst[i] = src[i];
}

// ---------------- host ----------------
static void* sym_addr(const void* symbol) {
    void* p = nullptr;
    cudaGetSymbolAddress(&p, symbol);
    return p;
}

extern "C" void kernel_launch(void* const* d_in, const int* in_sizes, int n_in,
                              void* d_out, int out_size) {
    (void)in_sizes; (void)n_in; (void)out_size;
    const float* x     = (const float*)d_in[0];
    const int*   ei    = (const int*)d_in[1];
    const float* eattr = (const float*)d_in[2];
    const float* wq  = (const float*)d_in[3];  const float* bq  = (const float*)d_in[4];
    const float* wk  = (const float*)d_in[5];  const float* bk  = (const float*)d_in[6];
    const float* wv  = (const float*)d_in[7];  const float* bv  = (const float*)d_in[8];
    const float* wao = (const float*)d_in[9];  const float* bao = (const float*)d_in[10];
    const float* ln1g = (const float*)d_in[11]; const float* ln1b = (const float*)d_in[12];
    const float* wint = (const float*)d_in[13]; const float* bint = (const float*)d_in[14];
    const float* wout = (const float*)d_in[15]; const float* bout = (const float*)d_in[16];
    const float* ln2g = (const float*)d_in[17]; const float* ln2b = (const float*)d_in[18];
    const float* wih = (const float*)d_in[19];  const float* whh = (const float*)d_in[20];
    const float* bih = (const float*)d_in[21];  const float* bhh = (const float*)d_in[22];
    const float* ln3g = (const float*)d_in[23]; const float* ln3b = (const float*)d_in[24];
    float* out = (float*)d_out;

    float* pQKV   = (float*)sym_addr(g_QKV);
    float* pEkv   = (float*)sym_addr(g_ekv);
    float* pAttraw= (float*)sym_addr(g_attraw);
    float* pPre   = (float*)sym_addr(g_pre);
    float* pAtt   = (float*)sym_addr(g_att);
    float* pInter = (float*)sym_addr(g_inter);
    float* pM     = (float*)sym_addr(g_m);
    float* pH     = (float*)sym_addr(g_hst);
    float* pX     = (float*)sym_addr(g_xst);
    float* pGi    = (float*)sym_addr(g_gi);
    float* pGh    = (float*)sym_addr(g_gh);
    float* pWqkv  = (float*)sym_addr(g_Wqkv);
    float* pBqkv  = (float*)sym_addr(g_bqkv);
    float* pWkve  = (float*)sym_addr(g_Wkve);
    float* pWao   = (float*)sym_addr(g_Wao);
    float* pWint  = (float*)sym_addr(g_Wint);
    float* pWout  = (float*)sym_addr(g_Wout);
    float* pWih   = (float*)sym_addr(g_Wih);
    float* pWhh   = (float*)sym_addr(g_Whh);
    int*   pCnt   = (int*)sym_addr(g_cnt);
    int*   pEidx  = (int*)sym_addr(g_eidxs);

    const int* src = ei;
    const int* dst = ei + EE;

    // --- weight prep (once per replay; tiny) ---
    build_wqkv_kernel<<<(384 * 128 + 255) / 256, 256>>>(wq, wk, wv);
    build_bqkv_kernel<<<2, 192>>>(bq, bk, bv);
    build_wkve_kernel<<<(256 * 128 + 255) / 256, 256>>>(wk, wv);
    transpose_kernel<<<(128 * 128 + 255) / 256, 256>>>(wao, pWao, 128, 128);
    transpose_kernel<<<(512 * 128 + 255) / 256, 256>>>(wint, pWint, 512, 128);
    transpose_kernel<<<(128 * 512 + 255) / 256, 256>>>(wout, pWout, 128, 512);
    transpose_kernel<<<(384 * 128 + 255) / 256, 256>>>(wih, pWih, 384, 128);
    transpose_kernel<<<(384 * 128 + 255) / 256, 256>>>(whh, pWhh, 384, 128);

    // --- CSR build by dst ---
    cudaMemsetAsync(pCnt, 0, NN * sizeof(int), 0);
    hist_kernel<<<(EE + 255) / 256, 256>>>(dst);
    scan_kernel<<<1, 1024>>>();
    scatter_kernel<<<(EE + 255) / 256, 256>>>(src, dst);

    // --- edge-invariant ekv = edge_attr @ [Wk|Wv]^T, gathered into CSR order ---
    gemm_kernel<0><<<dim3(EE / 128, 2), 256>>>(eattr, pWkve, nullptr, nullptr,
                                               pEkv, EE, 256, 128, pEidx);

    // --- init state ---
    copy4_kernel<<<(NN * 32 + 255) / 256, 256>>>((float4*)pX, (const float4*)x, NN * 32);
    copy4_kernel<<<(NN * 32 + 255) / 256, 256>>>((float4*)pH, (const float4*)x, NN * 32);

    const int MT = (NN + 127) / 128;       // 313
    const int WG = (NN * 32 + 255) / 256;  // warp-per-row grids (8 warps / 256-thr block)
    const int RG = (NN + 7) / 8;

    for (int t = 0; t < 3; t++) {
        // node QKV
        gemm_kernel<1><<<dim3(MT, 3), 256>>>(pX, pWqkv, pBqkv, nullptr, pQKV, NN, 384, 128, nullptr);
        // GAT attention
        gat_kernel<<<RG, 256>>>();
        // attn out proj + residual, then LN1
        gemm_kernel<2><<<dim3(MT, 1), 256>>>(pAttraw, pWao, bao, pX, pPre, NN, 128, 128, nullptr);
        ln_kernel<<<RG, 256>>>(pPre, ln1g, ln1b, pAtt);
        // FFN
        gemm_kernel<3><<<dim3(MT, 4), 256>>>(pAtt, pWint, bint, nullptr, pInter, NN, 512, 128, nullptr);
        gemm_kernel<2><<<dim3(MT, 1), 256>>>(pInter, pWout, bout, pAtt, pPre, NN, 128, 512, nullptr);
        ln_kernel<<<RG, 256>>>(pPre, ln2g, ln2b, pM);
        // GRU
        gemm_kernel<1><<<dim3(MT, 3), 256>>>(pM, pWih, bih, nullptr, pGi, NN, 384, 128, nullptr);
        gemm_kernel<1><<<dim3(MT, 3), 256>>>(pH, pWhh, bhh, nullptr, pGh, NN, 384, 128, nullptr);
        gru_ln_kernel<<<RG, 256>>>(ln3g, ln3b);
    }

    copy4_kernel<<<(NN * 32 + 255) / 256, 256>>>((float4*)out, (const float4*)pX, NN * 32);
    (void)WG;
}

// round 2
// speedup vs baseline: 1.0229x; 1.0229x over previous
#include <cuda_runtime.h>
#include <math.h>
#include <stdint.h>

#define NN 40000
#define EE 320000

// ---------------- scratch (device globals; no allocation allowed) ----------------
__device__ float g_QKV[NN * 384];           // per-node [Q(128)|K(128)|V(128)], Q pre-scaled by 1/sqrt(32)
__device__ float g_ekv[(long long)EE * 256];// per-sorted-edge [ek(128)|ev(128)]
__device__ float g_attraw[NN * 128];
__device__ float g_pre[NN * 128];
__device__ float g_att[NN * 128];
__device__ float g_inter[NN * 512];
__device__ float g_m[NN * 128];
__device__ float g_hst[NN * 128];
__device__ float g_xst[NN * 128];
__device__ float g_gi[NN * 384];
__device__ float g_gh[NN * 384];
__device__ float g_Wqkv[128 * 384];
__device__ float g_bqkv[384];
__device__ float g_Wkve[128 * 256];
__device__ float g_Wao[128 * 128];
__device__ float g_Wint[128 * 512];
__device__ float g_Wout[512 * 128];
__device__ float g_Wih[128 * 384];
__device__ float g_Whh[128 * 384];
__device__ int   g_cnt[NN];
__device__ int   g_rowptr[NN + 1];
__device__ int   g_cur[NN];
__device__ int   g_srcs[EE];
__device__ int   g_eidxs[EE];

// ---------------- tf32 helpers ----------------
__device__ __forceinline__ uint32_t f2tf(float x) {
    uint32_t r;
    asm("cvt.rna.tf32.f32 %0, %1;" : "=r"(r) : "f"(x));
    return r;
}

__device__ __forceinline__ void mma_tf32(float* d, const uint32_t* a, const uint32_t* b) {
    asm volatile(
        "mma.sync.aligned.m16n8k8.row.col.f32.tf32.tf32.f32 "
        "{%0,%1,%2,%3}, {%4,%5,%6,%7}, {%8,%9}, {%0,%1,%2,%3};"
        : "+f"(d[0]), "+f"(d[1]), "+f"(d[2]), "+f"(d[3])
        : "r"(a[0]), "r"(a[1]), "r"(a[2]), "r"(a[3]), "r"(b[0]), "r"(b[1]));
}

// ---------------- weight prep ----------------
__global__ void build_wqkv_kernel(const float* __restrict__ wq, const float* __restrict__ wk,
                                  const float* __restrict__ wv) {
    int idx = blockIdx.x * blockDim.x + threadIdx.x;
    if (idx >= 384 * 128) return;
    int n = idx / 128, k = idx % 128;
    const float SC = 0.17677669529663687f; // 1/sqrt(32)
    float v;
    if (n < 128)      v = wq[n * 128 + k] * SC;
    else if (n < 256) v = wk[(n - 128) * 128 + k];
    else              v = wv[(n - 256) * 128 + k];
    g_Wqkv[k * 384 + n] = v;
}

__global__ void build_bqkv_kernel(const float* __restrict__ bq, const float* __restrict__ bk,
                                  const float* __restrict__ bv) {
    int n = blockIdx.x * blockDim.x + threadIdx.x;
    if (n >= 384) return;
    const float SC = 0.17677669529663687f;
    float v;
    if (n < 128)      v = bq[n] * SC;
    else if (n < 256) v = bk[n - 128];
    else              v = bv[n - 256];
    g_bqkv[n] = v;
}

__global__ void build_wkve_kernel(const float* __restrict__ wk, const float* __restrict__ wv) {
    int idx = blockIdx.x * blockDim.x + threadIdx.x;
    if (idx >= 256 * 128) return;
    int n = idx / 128, k = idx % 128;
    float v = (n < 128) ? wk[n * 128 + k] : wv[(n - 128) * 128 + k];
    g_Wkve[k * 256 + n] = v;
}

// generic W[Nout,K] -> Wt[K,Nout]
__global__ void transpose_kernel(const float* __restrict__ W, float* __restrict__ Wt,
                                 int Nout, int K) {
    int idx = blockIdx.x * blockDim.x + threadIdx.x;
    if (idx >= Nout * K) return;
    int n = idx / K, k = idx % K;
    Wt[k * Nout + n] = W[idx];
}

// ---------------- CSR build ----------------
__global__ void hist_kernel(const int* __restrict__ dst) {
    int i = blockIdx.x * blockDim.x + threadIdx.x;
    if (i < EE) atomicAdd(&g_cnt[dst[i]], 1);
}

__global__ void scan_kernel() {
    __shared__ int part[1024];
    int t = threadIdx.x;
    const int per = (NN + 1023) / 1024;
    int base = t * per;
    int s = 0;
    for (int i = 0; i < per; i++) {
        int idx = base + i;
        if (idx < NN) s += g_cnt[idx];
    }
    part[t] = s;
    __syncthreads();
    if (t == 0) {
        int r = 0;
        for (int i = 0; i < 1024; i++) { int v = part[i]; part[i] = r; r += v; }
        g_rowptr[NN] = r;
    }
    __syncthreads();
    int r = part[t];
    for (int i = 0; i < per; i++) {
        int idx = base + i;
        if (idx < NN) {
            g_rowptr[idx] = r;
            g_cur[idx] = r;
            r += g_cnt[idx];
        }
    }
}

__global__ void scatter_kernel(const int* __restrict__ src, const int* __restrict__ dst) {
    int i = blockIdx.x * blockDim.x + threadIdx.x;
    if (i >= EE) return;
    int d = dst[i];
    int p = atomicAdd(&g_cur[d], 1);
    g_srcs[p] = src[i];
    g_eidxs[p] = i;
}

// ---------------- 3xTF32 tensor-core GEMM: C = A @ Wt (+bias, +res, gelu) ----------------
// Block tile 128x128, K-chunk 16. 8 warps: warp grid 4(M) x 2(N); warp tile 32x64
// = 2 m-tiles x 8 n-tiles of m16n8k8.
// A: [M,K] (rows optionally gathered via rowmap), Wt: [K,Nout], C: [M,Nout]
// EPI: 0 none, 1 bias, 2 bias+residual, 3 bias+gelu(exact)
template <int EPI>
__global__ void __launch_bounds__(256, 1) gemm_tf32_kernel(
    const float* __restrict__ A, const float* __restrict__ Wt,
    const float* __restrict__ bias, const float* __restrict__ res,
    float* __restrict__ C, int M, int Nout, int K,
    const int* __restrict__ rowmap)
{
    __shared__ float Ah[128][20];
    __shared__ float Al[128][20];
    __shared__ float Bh[16][136];
    __shared__ float Bl[16][136];

    const int tid  = threadIdx.x;
    const int warp = tid >> 5;
    const int lane = tid & 31;
    const int wm   = warp >> 1;          // 0..3
    const int wn   = warp & 1;           // 0..1
    const int lr   = lane >> 2;          // 0..7
    const int lk   = lane & 3;           // 0..3
    const int bm   = blockIdx.x * 128;
    const int bn   = blockIdx.y * 128;

    // A load mapping: each thread loads rows ma0 and ma0+64, 4 floats each per chunk
    const int ma0 = tid >> 2;
    const int kqa = (tid & 3) * 4;
    int ar0 = bm + ma0;        if (ar0 >= M) ar0 = M - 1;
    int ar1 = bm + ma0 + 64;   if (ar1 >= M) ar1 = M - 1;
    if (rowmap) { ar0 = rowmap[ar0]; ar1 = rowmap[ar1]; }
    const float* Ar0 = A + (size_t)ar0 * K + kqa;
    const float* Ar1 = A + (size_t)ar1 * K + kqa;

    // B load mapping: rows kb and kb+8, 4 floats each per chunk
    const int kb = tid >> 5;             // 0..7
    const int nq = (tid & 31) * 4;       // 0..124

    float acc[2][8][4];
#pragma unroll
    for (int i = 0; i < 2; i++)
#pragma unroll
        for (int j = 0; j < 8; j++)
#pragma unroll
            for (int l = 0; l < 4; l++) acc[i][j][l] = 0.f;

    for (int k0 = 0; k0 < K; k0 += 16) {
        // ---- global -> smem with hi/lo tf32 split ----
        float4 va0 = *(const float4*)(Ar0 + k0);
        float4 va1 = *(const float4*)(Ar1 + k0);
        float4 vb0 = *(const float4*)(Wt + (size_t)(k0 + kb) * Nout + bn + nq);
        float4 vb1 = *(const float4*)(Wt + (size_t)(k0 + kb + 8) * Nout + bn + nq);
        {
            const float* pa = (const float*)&va0;
#pragma unroll
            for (int j = 0; j < 4; j++) {
                uint32_t hb = f2tf(pa[j]);
                float hf = __uint_as_float(hb);
                Ah[ma0][kqa + j] = hf;
                Al[ma0][kqa + j] = __uint_as_float(f2tf(pa[j] - hf));
            }
            const float* pb = (const float*)&va1;
#pragma unroll
            for (int j = 0; j < 4; j++) {
                uint32_t hb = f2tf(pb[j]);
                float hf = __uint_as_float(hb);
                Ah[ma0 + 64][kqa + j] = hf;
                Al[ma0 + 64][kqa + j] = __uint_as_float(f2tf(pb[j] - hf));
            }
            const float* pc = (const float*)&vb0;
#pragma unroll
            for (int j = 0; j < 4; j++) {
                uint32_t hb = f2tf(pc[j]);
                float hf = __uint_as_float(hb);
                Bh[kb][nq + j] = hf;
                Bl[kb][nq + j] = __uint_as_float(f2tf(pc[j] - hf));
            }
            const float* pd = (const float*)&vb1;
#pragma unroll
            for (int j = 0; j < 4; j++) {
                uint32_t hb = f2tf(pd[j]);
                float hf = __uint_as_float(hb);
                Bh[kb + 8][nq + j] = hf;
                Bl[kb + 8][nq + j] = __uint_as_float(f2tf(pd[j] - hf));
            }
        }
        __syncthreads();

        // ---- two k8 steps per chunk ----
#pragma unroll
        for (int k8 = 0; k8 < 16; k8 += 8) {
            uint32_t ah[2][4], al[2][4], bhf[8][2], blf[8][2];
#pragma unroll
            for (int mt = 0; mt < 2; mt++) {
                int r = wm * 32 + mt * 16 + lr;
                ah[mt][0] = __float_as_uint(Ah[r][k8 + lk]);
                ah[mt][1] = __float_as_uint(Ah[r + 8][k8 + lk]);
                ah[mt][2] = __float_as_uint(Ah[r][k8 + lk + 4]);
                ah[mt][3] = __float_as_uint(Ah[r + 8][k8 + lk + 4]);
                al[mt][0] = __float_as_uint(Al[r][k8 + lk]);
                al[mt][1] = __float_as_uint(Al[r + 8][k8 + lk]);
                al[mt][2] = __float_as_uint(Al[r][k8 + lk + 4]);
                al[mt][3] = __float_as_uint(Al[r + 8][k8 + lk + 4]);
            }
#pragma unroll
            for (int nt = 0; nt < 8; nt++) {
                int c = wn * 64 + nt * 8 + lr;
                bhf[nt][0] = __float_as_uint(Bh[k8 + lk][c]);
                bhf[nt][1] = __float_as_uint(Bh[k8 + lk + 4][c]);
                blf[nt][0] = __float_as_uint(Bl[k8 + lk][c]);
                blf[nt][1] = __float_as_uint(Bl[k8 + lk + 4][c]);
            }
#pragma unroll
            for (int mt = 0; mt < 2; mt++)
#pragma unroll
                for (int nt = 0; nt < 8; nt++) {
                    mma_tf32(acc[mt][nt], ah[mt], bhf[nt]);
                    mma_tf32(acc[mt][nt], ah[mt], blf[nt]);
                    mma_tf32(acc[mt][nt], al[mt], bhf[nt]);
                }
        }
        __syncthreads();
    }

    // ---- epilogue ----
#pragma unroll
    for (int mt = 0; mt < 2; mt++) {
        int rbase = bm + wm * 32 + mt * 16 + lr;
#pragma unroll
        for (int half = 0; half < 2; half++) {
            int row = rbase + half * 8;
            if (row >= M) continue;
            float* Crow = C + (size_t)row * Nout + bn + wn * 64;
            const float* Rrow = (EPI == 2) ? (res + (size_t)row * Nout + bn + wn * 64) : nullptr;
#pragma unroll
            for (int nt = 0; nt < 8; nt++) {
                int c = nt * 8 + 2 * lk;
                float v0 = acc[mt][nt][half * 2 + 0];
                float v1 = acc[mt][nt][half * 2 + 1];
                if (EPI >= 1) {
                    v0 += bias[bn + wn * 64 + c];
                    v1 += bias[bn + wn * 64 + c + 1];
                }
                if (EPI == 2) { v0 += Rrow[c]; v1 += Rrow[c + 1]; }
                if (EPI == 3) {
                    v0 = 0.5f * v0 * (1.f + erff(v0 * 0.70710678118654752f));
                    v1 = 0.5f * v1 * (1.f + erff(v1 * 0.70710678118654752f));
                }
                *(float2*)(Crow + c) = make_float2(v0, v1);
            }
        }
    }
}

// ---------------- GAT: warp per node, online softmax over incoming edges ----------------
__global__ void gat_kernel() {
    int w = (blockIdx.x * blockDim.x + threadIdx.x) >> 5;
    int lane = threadIdx.x & 31;
    if (w >= NN) return;
    float q[4], mx[4], sm[4], acc[4];
#pragma unroll
    for (int h = 0; h < 4; h++) {
        q[h] = g_QKV[w * 384 + h * 32 + lane];
        mx[h] = -1e30f; sm[h] = 0.f; acc[h] = 0.f;
    }
    int beg = g_rowptr[w], end = g_rowptr[w + 1];
    for (int p = beg; p < end; p++) {
        int s = g_srcs[p];
        const float* kb = g_QKV + (size_t)s * 384 + 128;
        const float* eb = g_ekv + (size_t)p * 256;
        float kv[4], vv[4], d[4];
#pragma unroll
        for (int h = 0; h < 4; h++) {
            kv[h] = kb[h * 32 + lane] + eb[h * 32 + lane];
            vv[h] = kb[128 + h * 32 + lane] + eb[128 + h * 32 + lane];
            d[h] = q[h] * kv[h];
        }
#pragma unroll
        for (int off = 16; off > 0; off >>= 1)
#pragma unroll
            for (int h = 0; h < 4; h++)
                d[h] += __shfl_xor_sync(0xffffffffu, d[h], off);
#pragma unroll
        for (int h = 0; h < 4; h++) {
            float a = d[h];
            float nm = fmaxf(mx[h], a);
            float c = __expf(mx[h] - nm);
            float pe = __expf(a - nm);
            sm[h] = sm[h] * c + pe;
            acc[h] = acc[h] * c + pe * vv[h];
            mx[h] = nm;
        }
    }
#pragma unroll
    for (int h = 0; h < 4; h++)
        g_attraw[w * 128 + h * 32 + lane] = acc[h] / (sm[h] + 1e-16f);
}

// ---------------- LayerNorm: warp per row (H=128) ----------------
__global__ void ln_kernel(const float* __restrict__ in, const float* __restrict__ g,
                          const float* __restrict__ b, float* __restrict__ out) {
    int w = (blockIdx.x * blockDim.x + threadIdx.x) >> 5;
    int lane = threadIdx.x & 31;
    if (w >= NN) return;
    const float* row = in + (size_t)w * 128;
    float v[4];
    float s = 0.f;
#pragma unroll
    for (int j = 0; j < 4; j++) { v[j] = row[j * 32 + lane]; s += v[j]; }
#pragma unroll
    for (int off = 16; off > 0; off >>= 1) s += __shfl_xor_sync(0xffffffffu, s, off);
    float mean = s * (1.f / 128.f);
    float s2 = 0.f;
#pragma unroll
    for (int j = 0; j < 4; j++) { float d = v[j] - mean; s2 += d * d; }
#pragma unroll
    for (int off = 16; off > 0; off >>= 1) s2 += __shfl_xor_sync(0xffffffffu, s2, off);
    float inv = rsqrtf(s2 * (1.f / 128.f) + 1e-12f);
#pragma unroll
    for (int j = 0; j < 4; j++) {
        int e = j * 32 + lane;
        out[(size_t)w * 128 + e] = g[e] * (v[j] - mean) * inv + b[e];
    }
}

// ---------------- GRU gates + h update + LN3 -> x ----------------
__global__ void gru_ln_kernel(const float* __restrict__ lng, const float* __restrict__ lnb) {
    int w = (blockIdx.x * blockDim.x + threadIdx.x) >> 5;
    int lane = threadIdx.x & 31;
    if (w >= NN) return;
    float hn[4];
    float s = 0.f;
#pragma unroll
    for (int j = 0; j < 4; j++) {
        int e = j * 32 + lane;
        size_t b3 = (size_t)w * 384;
        float ir = g_gi[b3 + e], iz = g_gi[b3 + 128 + e], in_ = g_gi[b3 + 256 + e];
        float hr = g_gh[b3 + e], hz = g_gh[b3 + 128 + e], hnn = g_gh[b3 + 256 + e];
        float hv = g_hst[(size_t)w * 128 + e];
        float r = 1.f / (1.f + expf(-(ir + hr)));
        float z = 1.f / (1.f + expf(-(iz + hz)));
        float n = tanhf(in_ + r * hnn);
        float hnew = (1.f - z) * n + z * hv;
        g_hst[(size_t)w * 128 + e] = hnew;
        hn[j] = hnew;
        s += hnew;
    }
#pragma unroll
    for (int off = 16; off > 0; off >>= 1) s += __shfl_xor_sync(0xffffffffu, s, off);
    float mean = s * (1.f / 128.f);
    float s2 = 0.f;
#pragma unroll
    for (int j = 0; j < 4; j++) { float d = hn[j] - mean; s2 += d * d; }
#pragma unroll
    for (int off = 16; off > 0; off >>= 1) s2 += __shfl_xor_sync(0xffffffffu, s2, off);
    float inv = rsqrtf(s2 * (1.f / 128.f) + 1e-12f);
#pragma unroll
    for (int j = 0; j < 4; j++) {
        int e = j * 32 + lane;
        g_xst[(size_t)w * 128 + e] = lng[e] * (hn[j] - mean) * inv + lnb[e];
    }
}

__global__ void copy4_kernel(float4* __restrict__ dst, const float4* __restrict__ src, int n) {
    int i = blockIdx.x * blockDim.x + threadIdx.x;
    if (i < n) dst[i] = src[i];
}

// ---------------- host ----------------
static void* sym_addr(const void* symbol) {
    void* p = nullptr;
    cudaGetSymbolAddress(&p, symbol);
    return p;
}

extern "C" void kernel_launch(void* const* d_in, const int* in_sizes, int n_in,
                              void* d_out, int out_size) {
    (void)in_sizes; (void)n_in; (void)out_size;
    const float* x     = (const float*)d_in[0];
    const int*   ei    = (const int*)d_in[1];
    const float* eattr = (const float*)d_in[2];
    const float* wq  = (const float*)d_in[3];  const float* bq  = (const float*)d_in[4];
    const float* wk  = (const float*)d_in[5];  const float* bk  = (const float*)d_in[6];
    const float* wv  = (const float*)d_in[7];  const float* bv  = (const float*)d_in[8];
    const float* wao = (const float*)d_in[9];  const float* bao = (const float*)d_in[10];
    const float* ln1g = (const float*)d_in[11]; const float* ln1b = (const float*)d_in[12];
    const float* wint = (const float*)d_in[13]; const float* bint = (const float*)d_in[14];
    const float* wout = (const float*)d_in[15]; const float* bout = (const float*)d_in[16];
    const float* ln2g = (const float*)d_in[17]; const float* ln2b = (const float*)d_in[18];
    const float* wih = (const float*)d_in[19];  const float* whh = (const float*)d_in[20];
    const float* bih = (const float*)d_in[21];  const float* bhh = (const float*)d_in[22];
    const float* ln3g = (const float*)d_in[23]; const float* ln3b = (const float*)d_in[24];
    float* out = (float*)d_out;

    float* pQKV   = (float*)sym_addr(g_QKV);
    float* pEkv   = (float*)sym_addr(g_ekv);
    float* pAttraw= (float*)sym_addr(g_attraw);
    float* pPre   = (float*)sym_addr(g_pre);
    float* pAtt   = (float*)sym_addr(g_att);
    float* pInter = (float*)sym_addr(g_inter);
    float* pM     = (float*)sym_addr(g_m);
    float* pH     = (float*)sym_addr(g_hst);
    float* pX     = (float*)sym_addr(g_xst);
    float* pGi    = (float*)sym_addr(g_gi);
    float* pGh    = (float*)sym_addr(g_gh);
    float* pWqkv  = (float*)sym_addr(g_Wqkv);
    float* pBqkv  = (float*)sym_addr(g_bqkv);
    float* pWkve  = (float*)sym_addr(g_Wkve);
    float* pWao   = (float*)sym_addr(g_Wao);
    float* pWint  = (float*)sym_addr(g_Wint);
    float* pWout  = (float*)sym_addr(g_Wout);
    float* pWih   = (float*)sym_addr(g_Wih);
    float* pWhh   = (float*)sym_addr(g_Whh);
    int*   pCnt   = (int*)sym_addr(g_cnt);
    int*   pEidx  = (int*)sym_addr(g_eidxs);

    const int* src = ei;
    const int* dst = ei + EE;

    // --- weight prep (tiny) ---
    build_wqkv_kernel<<<(384 * 128 + 255) / 256, 256>>>(wq, wk, wv);
    build_bqkv_kernel<<<2, 192>>>(bq, bk, bv);
    build_wkve_kernel<<<(256 * 128 + 255) / 256, 256>>>(wk, wv);
    transpose_kernel<<<(128 * 128 + 255) / 256, 256>>>(wao, pWao, 128, 128);
    transpose_kernel<<<(512 * 128 + 255) / 256, 256>>>(wint, pWint, 512, 128);
    transpose_kernel<<<(128 * 512 + 255) / 256, 256>>>(wout, pWout, 128, 512);
    transpose_kernel<<<(384 * 128 + 255) / 256, 256>>>(wih, pWih, 384, 128);
    transpose_kernel<<<(384 * 128 + 255) / 256, 256>>>(whh, pWhh, 384, 128);

    // --- CSR build by dst ---
    cudaMemsetAsync(pCnt, 0, NN * sizeof(int), 0);
    hist_kernel<<<(EE + 255) / 256, 256>>>(dst);
    scan_kernel<<<1, 1024>>>();
    scatter_kernel<<<(EE + 255) / 256, 256>>>(src, dst);

    // --- edge-invariant ekv = edge_attr @ [Wk|Wv]^T, gathered into CSR order ---
    gemm_tf32_kernel<0><<<dim3(EE / 128, 2), 256>>>(eattr, pWkve, nullptr, nullptr,
                                                    pEkv, EE, 256, 128, pEidx);

    // --- init state ---
    copy4_kernel<<<(NN * 32 + 255) / 256, 256>>>((float4*)pX, (const float4*)x, NN * 32);
    copy4_kernel<<<(NN * 32 + 255) / 256, 256>>>((float4*)pH, (const float4*)x, NN * 32);

    const int MT = (NN + 127) / 128;       // 313
    const int RG = (NN + 7) / 8;

    for (int t = 0; t < 3; t++) {
        // node QKV
        gemm_tf32_kernel<1><<<dim3(MT, 3), 256>>>(pX, pWqkv, pBqkv, nullptr, pQKV, NN, 384, 128, nullptr);
        // GAT attention
        gat_kernel<<<RG, 256>>>();
        // attn out proj + residual, then LN1
        gemm_tf32_kernel<2><<<dim3(MT, 1), 256>>>(pAttraw, pWao, bao, pX, pPre, NN, 128, 128, nullptr);
        ln_kernel<<<RG, 256>>>(pPre, ln1g, ln1b, pAtt);
        // FFN
        gemm_tf32_kernel<3><<<dim3(MT, 4), 256>>>(pAtt, pWint, bint, nullptr, pInter, NN, 512, 128, nullptr);
        gemm_tf32_kernel<2><<<dim3(MT, 1), 256>>>(pInter, pWout, bout, pAtt, pPre, NN, 128, 512, nullptr);
        ln_kernel<<<RG, 256>>>(pPre, ln2g, ln2b, pM);
        // GRU
        gemm_tf32_kernel<1><<<dim3(MT, 3), 256>>>(pM, pWih, bih, nullptr, pGi, NN, 384, 128, nullptr);
        gemm_tf32_kernel<1><<<dim3(MT, 3), 256>>>(pH, pWhh, bhh, nullptr, pGh, NN, 384, 128, nullptr);
        gru_ln_kernel<<<RG, 256>>>(ln3g, ln3b);
    }

    copy4_kernel<<<(NN * 32 + 255) / 256, 256>>>((float4*)out, (const float4*)pX, NN * 32);
}

// round 4
// speedup vs baseline: 1.4465x; 1.4142x over previous
#include <cuda_runtime.h>
#include <cuda_bf16.h>
#include <math.h>
#include <stdint.h>

#define NN 40000
#define EE 320000

// ---------------- device scratch ----------------
__device__ float g_P[(size_t)NN * 768];     // [q(128,scaled,biased) | k(128,biased) | qe(512)]
__device__ float g_sxe[(size_t)NN * 512];   // per-head weighted sums of (x_src + e)
__device__ float g_pre[NN * 128];
__device__ float g_att[NN * 128];
__device__ float g_inter[(size_t)NN * 512];
__device__ float g_m[NN * 128];
__device__ float g_h[NN * 128];
__device__ float g_x[NN * 128];
__device__ float g_gi[(size_t)NN * 384];
__device__ float g_gh[(size_t)NN * 384];
__device__ float g_WprojF[768 * 128];
__device__ float g_Wav4F[128 * 512];
__device__ float g_bproj[768];
__device__ float g_bav[128];
// bf16 hi/lo tile images: 48 tiles x (128 rows x 36 words)
__device__ uint32_t g_imgH[48 * 4608];
__device__ uint32_t g_imgL[48 * 4608];
__device__ int g_cnt[NN], g_rowptr[NN + 1], g_cur[NN], g_srcs[EE], g_eidxs[EE];

#define TILE_PROJ 0
#define TILE_WAV4 12
#define TILE_WINT 20
#define TILE_WOUT 28
#define TILE_WIH  36
#define TILE_WHH  42

// ---------------- helpers ----------------
__device__ __forceinline__ void bf16_split2(float a, float b, uint32_t& hi, uint32_t& lo) {
    __nv_bfloat16 ha = __float2bfloat16(a), hb = __float2bfloat16(b);
    float ra = a - __bfloat162float(ha), rb = b - __bfloat162float(hb);
    __nv_bfloat16 la = __float2bfloat16(ra), lb = __float2bfloat16(rb);
    hi = (uint32_t)__bfloat16_as_ushort(ha) | ((uint32_t)__bfloat16_as_ushort(hb) << 16);
    lo = (uint32_t)__bfloat16_as_ushort(la) | ((uint32_t)__bfloat16_as_ushort(lb) << 16);
}
__device__ __forceinline__ void mma_bf16(float* d, const uint32_t* a, const uint32_t* b) {
    asm volatile(
        "mma.sync.aligned.m16n8k16.row.col.f32.bf16.bf16.f32 "
        "{%0,%1,%2,%3}, {%4,%5,%6,%7}, {%8,%9}, {%0,%1,%2,%3};"
        : "+f"(d[0]), "+f"(d[1]), "+f"(d[2]), "+f"(d[3])
        : "r"(a[0]), "r"(a[1]), "r"(a[2]), "r"(a[3]), "r"(b[0]), "r"(b[1]));
}

// ---------------- weight prep ----------------
// combined proj weight [768 x 128]: rows 0-127 Wq*SC, 128-255 Wk, 256-767 M_h = SC*Wk_h^T Wq_h
__global__ void build_projf(const float* __restrict__ wq, const float* __restrict__ wk) {
    int idx = blockIdx.x * blockDim.x + threadIdx.x;
    if (idx >= 768 * 128) return;
    int n = idx >> 7, k = idx & 127;
    const float SC = 0.17677669529663687f;
    float v;
    if (n < 128) v = wq[n * 128 + k] * SC;
    else if (n < 256) v = wk[(n - 128) * 128 + k];
    else {
        int h = (n - 256) >> 7, d1 = (n - 256) & 127;
        float s = 0.f;
        for (int r = 0; r < 32; r++)
            s += wk[(h * 32 + r) * 128 + d1] * wq[(h * 32 + r) * 128 + k];
        v = s * SC;
    }
    g_WprojF[idx] = v;
}
__global__ void build_bproj(const float* __restrict__ bq, const float* __restrict__ bk,
                            const float* __restrict__ wk) {
    int n = blockIdx.x * blockDim.x + threadIdx.x;
    if (n >= 768) return;
    const float SC = 0.17677669529663687f;
    float v;
    if (n < 128) v = bq[n] * SC;
    else if (n < 256) v = bk[n - 128];
    else {
        int h = (n - 256) >> 7, d1 = (n - 256) & 127;
        float s = 0.f;
        for (int r = 0; r < 32; r++)
            s += wk[(h * 32 + r) * 128 + d1] * bq[h * 32 + r];
        v = s * SC;
    }
    g_bproj[n] = v;
}
// Wav4 [128 x 512]: Wav4[n][h*128+d] = sum_r Wao[n, h*32+r] * Wv[h*32+r, d]
__global__ void build_wav4f(const float* __restrict__ wao, const float* __restrict__ wv) {
    int idx = blockIdx.x * blockDim.x + threadIdx.x;
    if (idx >= 128 * 512) return;
    int n = idx >> 9, m = idx & 511;
    int h = m >> 7, d = m & 127;
    float s = 0.f;
    for (int r = 0; r < 32; r++)
        s += wao[n * 128 + h * 32 + r] * wv[(h * 32 + r) * 128 + d];
    g_Wav4F[idx] = s;
}
__global__ void build_bav(const float* __restrict__ wao, const float* __restrict__ bv,
                          const float* __restrict__ bao) {
    int n = blockIdx.x * blockDim.x + threadIdx.x;
    if (n >= 128) return;
    float s = 0.f;
    for (int k = 0; k < 128; k++) s += wao[n * 128 + k] * bv[k];
    g_bav[n] = s + bao[n];
}
// fp32 [Nout x K] -> bf16 hi/lo tile images (row-major within tile, 36-word padded rows)
__global__ void prep_w(const float* __restrict__ src, int Nout, int K, int tileOff) {
    int idx = blockIdx.x * blockDim.x + threadIdx.x;
    if (idx >= Nout * K) return;
    int n = idx / K, k = idx % K;
    float v = src[idx];
    __nv_bfloat16 h = __float2bfloat16(v);
    __nv_bfloat16 l = __float2bfloat16(v - __bfloat162float(h));
    int tile = tileOff + (n >> 7) * (K >> 6) + (k >> 6);
    size_t half_idx = ((size_t)tile * 4608 + (n & 127) * 36 + ((k & 63) >> 1)) * 2 + (k & 1);
    ((unsigned short*)g_imgH)[half_idx] = __bfloat16_as_ushort(h);
    ((unsigned short*)g_imgL)[half_idx] = __bfloat16_as_ushort(l);
}

// ---------------- CSR build ----------------
__global__ void hist_kernel(const int* __restrict__ dst) {
    int i = blockIdx.x * blockDim.x + threadIdx.x;
    if (i < EE) atomicAdd(&g_cnt[dst[i]], 1);
}
__global__ void scan_kernel() {
    __shared__ int part[1024];
    int t = threadIdx.x;
    const int per = (NN + 1023) / 1024;
    int base = t * per, s = 0;
    for (int i = 0; i < per; i++) { int idx = base + i; if (idx < NN) s += g_cnt[idx]; }
    part[t] = s;
    __syncthreads();
    if (t == 0) {
        int r = 0;
        for (int i = 0; i < 1024; i++) { int v = part[i]; part[i] = r; r += v; }
        g_rowptr[NN] = r;
    }
    __syncthreads();
    int r = part[t];
    for (int i = 0; i < per; i++) {
        int idx = base + i;
        if (idx < NN) { g_rowptr[idx] = r; g_cur[idx] = r; r += g_cnt[idx]; }
    }
}
__global__ void scatter_kernel(const int* __restrict__ src, const int* __restrict__ dst) {
    int i = blockIdx.x * blockDim.x + threadIdx.x;
    if (i >= EE) return;
    int d = dst[i];
    int p = atomicAdd(&g_cur[d], 1);
    g_srcs[p] = src[i];
    g_eidxs[p] = i;
}

// ---------------- bf16 3-term mma.sync GEMM ----------------
// C[M, ntiles*128] = A[M,lda-stride] @ W^T, W given as pre-swizzled hi/lo tile images.
// Block: 128x128 out tile; 8 warps (4m x 2n); warp tile 32x64 = 2x8 m16n8k16 tiles.
// EPI: 1 bias, 2 bias+residual, 3 bias+gelu(exact)
template <int EPI>
__global__ void __launch_bounds__(256) gemm_bf16(
    const float* __restrict__ A, int lda,
    const uint32_t* __restrict__ imgH, const uint32_t* __restrict__ imgL,
    const float* __restrict__ bias, const float* __restrict__ res,
    float* __restrict__ out, int M, int KC, int ldo)
{
    extern __shared__ uint32_t smw[];
    uint32_t* AhS = smw;
    uint32_t* AlS = smw + 4608;
    uint32_t* BhS = smw + 2 * 4608;
    uint32_t* BlS = smw + 3 * 4608;

    const int tid = threadIdx.x;
    const int warp = tid >> 5, lane = tid & 31;
    const int wm = warp >> 1, wn = warp & 1;
    const int lr = lane >> 2, lk = lane & 3;
    const int bm = blockIdx.x * 128;

    float acc[2][8][4];
#pragma unroll
    for (int i = 0; i < 2; i++)
#pragma unroll
        for (int j = 0; j < 8; j++)
#pragma unroll
            for (int l = 0; l < 4; l++) acc[i][j][l] = 0.f;

    const int arow = tid >> 1, aseg = tid & 1;
    int gr = bm + arow;
    if (gr >= M) gr = M - 1;
    const float* asrc = A + (size_t)gr * lda + aseg * 32;
    uint32_t* dh = AhS + arow * 36 + aseg * 16;
    uint32_t* dl = AlS + arow * 36 + aseg * 16;

    for (int c = 0; c < KC; c++) {
        // A fill: fp32 -> bf16 hi/lo planes
        const float* s0 = asrc + c * 64;
#pragma unroll
        for (int p = 0; p < 16; p += 2) {
            float4 f = *(const float4*)(s0 + 2 * p);
            uint32_t h0, l0, h1, l1;
            bf16_split2(f.x, f.y, h0, l0);
            bf16_split2(f.z, f.w, h1, l1);
            dh[p] = h0; dh[p + 1] = h1;
            dl[p] = l0; dl[p + 1] = l1;
        }
        // B fill: raw copy of pre-swizzled images
        {
            const uint32_t* sh = imgH + (size_t)(blockIdx.y * KC + c) * 4608;
            const uint32_t* sl = imgL + (size_t)(blockIdx.y * KC + c) * 4608;
#pragma unroll
            for (int it = 0; it < 18; it++) {
                int i = it * 256 + tid;
                BhS[i] = sh[i];
                BlS[i] = sl[i];
            }
        }
        __syncthreads();

#pragma unroll
        for (int s = 0; s < 4; s++) {
            const int akp = s * 8 + lk;
            uint32_t ah[2][4], al[2][4], bh[8][2], bl[8][2];
#pragma unroll
            for (int mt = 0; mt < 2; mt++) {
                const uint32_t* b1 = AhS + (wm * 32 + mt * 16 + lr) * 36 + akp;
                ah[mt][0] = b1[0]; ah[mt][1] = b1[288]; ah[mt][2] = b1[4]; ah[mt][3] = b1[292];
                const uint32_t* b2 = AlS + (wm * 32 + mt * 16 + lr) * 36 + akp;
                al[mt][0] = b2[0]; al[mt][1] = b2[288]; al[mt][2] = b2[4]; al[mt][3] = b2[292];
            }
#pragma unroll
            for (int nt = 0; nt < 8; nt++) {
                const uint32_t* bb = BhS + (wn * 64 + nt * 8 + lr) * 36 + akp;
                bh[nt][0] = bb[0]; bh[nt][1] = bb[4];
                const uint32_t* b2 = BlS + (wn * 64 + nt * 8 + lr) * 36 + akp;
                bl[nt][0] = b2[0]; bl[nt][1] = b2[4];
            }
#pragma unroll
            for (int mt = 0; mt < 2; mt++)
#pragma unroll
                for (int nt = 0; nt < 8; nt++) {
                    mma_bf16(acc[mt][nt], ah[mt], bh[nt]);
                    mma_bf16(acc[mt][nt], ah[mt], bl[nt]);
                    mma_bf16(acc[mt][nt], al[mt], bh[nt]);
                }
        }
        __syncthreads();
    }

    // epilogue
    const int cbase = blockIdx.y * 128 + wn * 64;
#pragma unroll
    for (int mt = 0; mt < 2; mt++) {
        int r0 = bm + wm * 32 + mt * 16 + lr;
#pragma unroll
        for (int half = 0; half < 2; half++) {
            int row = r0 + half * 8;
            if (row >= M) continue;
            float* orow = out + (size_t)row * ldo + cbase;
            const float* rrow = (EPI == 2) ? (res + (size_t)row * ldo + cbase) : nullptr;
#pragma unroll
            for (int nt = 0; nt < 8; nt++) {
                int cl = nt * 8 + lk * 2;
                float v0 = acc[mt][nt][half * 2 + 0];
                float v1 = acc[mt][nt][half * 2 + 1];
                v0 += bias[cbase + cl];
                v1 += bias[cbase + cl + 1];
                if (EPI == 2) { v0 += rrow[cl]; v1 += rrow[cl + 1]; }
                if (EPI == 3) {
                    v0 = 0.5f * v0 * (1.f + erff(v0 * 0.70710678118654752f));
                    v1 = 0.5f * v1 * (1.f + erff(v1 * 0.70710678118654752f));
                }
                *(float2*)(orow + cl) = make_float2(v0, v1);
            }
        }
    }
}

// ---------------- GAT: warp per node, per-head online softmax, accumulates (x_src+e) ----------------
__global__ void gat2_kernel(const float* __restrict__ eattr) {
    int w = (blockIdx.x * blockDim.x + threadIdx.x) >> 5;
    int lane = threadIdx.x & 31;
    if (w >= NN) return;
    float q[4], qe[4][4], mx[4], smx[4], acc[4][4];
    const float* Pw = g_P + (size_t)w * 768;
#pragma unroll
    for (int j = 0; j < 4; j++) q[j] = Pw[j * 32 + lane];
#pragma unroll
    for (int h = 0; h < 4; h++) {
#pragma unroll
        for (int j = 0; j < 4; j++) {
            qe[h][j] = Pw[256 + h * 128 + j * 32 + lane];
            acc[h][j] = 0.f;
        }
        mx[h] = -1e30f; smx[h] = 0.f;
    }
    int beg = g_rowptr[w], end = g_rowptr[w + 1];
    for (int p = beg; p < end; p++) {
        int s = g_srcs[p], ei = g_eidxs[p];
        const float* kp = g_P + (size_t)s * 768 + 128;
        const float* xp = g_x + (size_t)s * 128;
        const float* ep = eattr + (size_t)ei * 128;
        float ks[4], ev[4], u[4];
#pragma unroll
        for (int j = 0; j < 4; j++) {
            ks[j] = kp[j * 32 + lane];
            ev[j] = ep[j * 32 + lane];
            u[j] = xp[j * 32 + lane] + ev[j];
        }
        float d[4];
#pragma unroll
        for (int h = 0; h < 4; h++)
            d[h] = q[h] * ks[h] + qe[h][0] * ev[0] + qe[h][1] * ev[1]
                 + qe[h][2] * ev[2] + qe[h][3] * ev[3];
#pragma unroll
        for (int off = 16; off > 0; off >>= 1)
#pragma unroll
            for (int h = 0; h < 4; h++)
                d[h] += __shfl_xor_sync(0xffffffffu, d[h], off);
#pragma unroll
        for (int h = 0; h < 4; h++) {
            float a = d[h];
            float nm = fmaxf(mx[h], a);
            float csc = __expf(mx[h] - nm);
            float pe = __expf(a - nm);
            smx[h] = smx[h] * csc + pe;
#pragma unroll
            for (int j = 0; j < 4; j++)
                acc[h][j] = acc[h][j] * csc + pe * u[j];
            mx[h] = nm;
        }
    }
    float* o = g_sxe + (size_t)w * 512;
#pragma unroll
    for (int h = 0; h < 4; h++) {
        float inv = 1.f / (smx[h] + 1e-16f);
#pragma unroll
        for (int j = 0; j < 4; j++)
            o[h * 128 + j * 32 + lane] = acc[h][j] * inv;
    }
}

// ---------------- LayerNorm: warp per row ----------------
__global__ void ln_kernel(const float* __restrict__ in, const float* __restrict__ g,
                          const float* __restrict__ b, float* __restrict__ out) {
    int w = (blockIdx.x * blockDim.x + threadIdx.x) >> 5;
    int lane = threadIdx.x & 31;
    if (w >= NN) return;
    const float* row = in + (size_t)w * 128;
    float v[4], s = 0.f;
#pragma unroll
    for (int j = 0; j < 4; j++) { v[j] = row[j * 32 + lane]; s += v[j]; }
#pragma unroll
    for (int off = 16; off > 0; off >>= 1) s += __shfl_xor_sync(0xffffffffu, s, off);
    float mean = s * (1.f / 128.f), s2 = 0.f;
#pragma unroll
    for (int j = 0; j < 4; j++) { float d = v[j] - mean; s2 += d * d; }
#pragma unroll
    for (int off = 16; off > 0; off >>= 1) s2 += __shfl_xor_sync(0xffffffffu, s2, off);
    float inv = rsqrtf(s2 * (1.f / 128.f) + 1e-12f);
#pragma unroll
    for (int j = 0; j < 4; j++) {
        int e = j * 32 + lane;
        out[(size_t)w * 128 + e] = g[e] * (v[j] - mean) * inv + b[e];
    }
}

// ---------------- GRU + LN3 ----------------
__global__ void gru_ln_kernel(const float* __restrict__ lng, const float* __restrict__ lnb) {
    int w = (blockIdx.x * blockDim.x + threadIdx.x) >> 5;
    int lane = threadIdx.x & 31;
    if (w >= NN) return;
    float hn[4], s = 0.f;
#pragma unroll
    for (int j = 0; j < 4; j++) {
        int e = j * 32 + lane;
        size_t b3 = (size_t)w * 384;
        float ir = g_gi[b3 + e], iz = g_gi[b3 + 128 + e], in_ = g_gi[b3 + 256 + e];
        float hr = g_gh[b3 + e], hz = g_gh[b3 + 128 + e], hnn = g_gh[b3 + 256 + e];
        float hv = g_h[(size_t)w * 128 + e];
        float r = 1.f / (1.f + expf(-(ir + hr)));
        float z = 1.f / (1.f + expf(-(iz + hz)));
        float n = tanhf(in_ + r * hnn);
        float hnew = (1.f - z) * n + z * hv;
        g_h[(size_t)w * 128 + e] = hnew;
        hn[j] = hnew;
        s += hnew;
    }
#pragma unroll
    for (int off = 16; off > 0; off >>= 1) s += __shfl_xor_sync(0xffffffffu, s, off);
    float mean = s * (1.f / 128.f), s2 = 0.f;
#pragma unroll
    for (int j = 0; j < 4; j++) { float d = hn[j] - mean; s2 += d * d; }
#pragma unroll
    for (int off = 16; off > 0; off >>= 1) s2 += __shfl_xor_sync(0xffffffffu, s2, off);
    float inv = rsqrtf(s2 * (1.f / 128.f) + 1e-12f);
#pragma unroll
    for (int j = 0; j < 4; j++) {
        int e = j * 32 + lane;
        g_x[(size_t)w * 128 + e] = lng[e] * (hn[j] - mean) * inv + lnb[e];
    }
}

__global__ void copy4_kernel(float4* __restrict__ dst, const float4* __restrict__ src, int n) {
    int i = blockIdx.x * blockDim.x + threadIdx.x;
    if (i < n) dst[i] = src[i];
}

// ---------------- host ----------------
static void* sym_addr(const void* symbol) {
    void* p = nullptr;
    cudaGetSymbolAddress(&p, symbol);
    return p;
}

extern "C" void kernel_launch(void* const* d_in, const int* in_sizes, int n_in,
                              void* d_out, int out_size) {
    (void)in_sizes; (void)n_in; (void)out_size;
    const float* x     = (const float*)d_in[0];
    const int*   ei    = (const int*)d_in[1];
    const float* eattr = (const float*)d_in[2];
    const float* wq  = (const float*)d_in[3];  const float* bq  = (const float*)d_in[4];
    const float* wk  = (const float*)d_in[5];  const float* bk  = (const float*)d_in[6];
    const float* wv  = (const float*)d_in[7];  const float* bv  = (const float*)d_in[8];
    const float* wao = (const float*)d_in[9];  const float* bao = (const float*)d_in[10];
    const float* ln1g = (const float*)d_in[11]; const float* ln1b = (const float*)d_in[12];
    const float* wint = (const float*)d_in[13]; const float* bint = (const float*)d_in[14];
    const float* wout = (const float*)d_in[15]; const float* bout = (const float*)d_in[16];
    const float* ln2g = (const float*)d_in[17]; const float* ln2b = (const float*)d_in[18];
    const float* wih = (const float*)d_in[19];  const float* whh = (const float*)d_in[20];
    const float* bih = (const float*)d_in[21];  const float* bhh = (const float*)d_in[22];
    const float* ln3g = (const float*)d_in[23]; const float* ln3b = (const float*)d_in[24];
    float* out = (float*)d_out;

    float* pP    = (float*)sym_addr(g_P);
    float* pSxe  = (float*)sym_addr(g_sxe);
    float* pPre  = (float*)sym_addr(g_pre);
    float* pAtt  = (float*)sym_addr(g_att);
    float* pInt  = (float*)sym_addr(g_inter);
    float* pM    = (float*)sym_addr(g_m);
    float* pH    = (float*)sym_addr(g_h);
    float* pX    = (float*)sym_addr(g_x);
    float* pGi   = (float*)sym_addr(g_gi);
    float* pGh   = (float*)sym_addr(g_gh);
    float* pWprojF = (float*)sym_addr(g_WprojF);
    float* pWav4F  = (float*)sym_addr(g_Wav4F);
    float* pBproj  = (float*)sym_addr(g_bproj);
    float* pBav    = (float*)sym_addr(g_bav);
    uint32_t* pImgH = (uint32_t*)sym_addr(g_imgH);
    uint32_t* pImgL = (uint32_t*)sym_addr(g_imgL);
    int* pCnt = (int*)sym_addr(g_cnt);

    const int* srcp = ei;
    const int* dstp = ei + EE;

    const int SMB = 4 * 4608 * 4;  // 73728 B dynamic smem
    cudaFuncSetAttribute(gemm_bf16<1>, cudaFuncAttributeMaxDynamicSharedMemorySize, SMB);
    cudaFuncSetAttribute(gemm_bf16<2>, cudaFuncAttributeMaxDynamicSharedMemorySize, SMB);
    cudaFuncSetAttribute(gemm_bf16<3>, cudaFuncAttributeMaxDynamicSharedMemorySize, SMB);

    // --- prep: fold weights ---
    build_projf<<<(768 * 128 + 255) / 256, 256>>>(wq, wk);
    build_bproj<<<3, 256>>>(bq, bk, wk);
    build_wav4f<<<(128 * 512 + 255) / 256, 256>>>(wao, wv);
    build_bav<<<1, 128>>>(wao, bv, bao);
    prep_w<<<(768 * 128 + 255) / 256, 256>>>(pWprojF, 768, 128, TILE_PROJ);
    prep_w<<<(128 * 512 + 255) / 256, 256>>>(pWav4F, 128, 512, TILE_WAV4);
    prep_w<<<(512 * 128 + 255) / 256, 256>>>(wint, 512, 128, TILE_WINT);
    prep_w<<<(128 * 512 + 255) / 256, 256>>>(wout, 128, 512, TILE_WOUT);
    prep_w<<<(384 * 128 + 255) / 256, 256>>>(wih, 384, 128, TILE_WIH);
    prep_w<<<(384 * 128 + 255) / 256, 256>>>(whh, 384, 128, TILE_WHH);

    // --- CSR build by dst ---
    cudaMemsetAsync(pCnt, 0, NN * sizeof(int), 0);
    hist_kernel<<<(EE + 255) / 256, 256>>>(dstp);
    scan_kernel<<<1, 1024>>>();
    scatter_kernel<<<(EE + 255) / 256, 256>>>(srcp, dstp);

    // --- init state ---
    copy4_kernel<<<(NN * 32 + 255) / 256, 256>>>((float4*)pX, (const float4*)x, NN * 32);
    copy4_kernel<<<(NN * 32 + 255) / 256, 256>>>((float4*)pH, (const float4*)x, NN * 32);

    const int MT = (NN + 127) / 128;   // 313
    const int RG = (NN + 7) / 8;

    for (int t = 0; t < 3; t++) {
        // proj: x @ [Wq|Wk|M]^T -> P (N x 768)
        gemm_bf16<1><<<dim3(MT, 6), 256, SMB>>>(pX, 128, pImgH + (size_t)TILE_PROJ * 4608,
            pImgL + (size_t)TILE_PROJ * 4608, pBproj, nullptr, pP, NN, 2, 768);
        // GAT -> sxe (N x 512)
        gat2_kernel<<<RG, 256>>>(eattr);
        // fused attn-out: sxe @ Wav4^T + bav + x
        gemm_bf16<2><<<dim3(MT, 1), 256, SMB>>>(pSxe, 512, pImgH + (size_t)TILE_WAV4 * 4608,
            pImgL + (size_t)TILE_WAV4 * 4608, pBav, pX, pPre, NN, 8, 128);
        ln_kernel<<<RG, 256>>>(pPre, ln1g, ln1b, pAtt);
        // FFN
        gemm_bf16<3><<<dim3(MT, 4), 256, SMB>>>(pAtt, 128, pImgH + (size_t)TILE_WINT * 4608,
            pImgL + (size_t)TILE_WINT * 4608, bint, nullptr, pInt, NN, 2, 512);
        gemm_bf16<2><<<dim3(MT, 1), 256, SMB>>>(pInt, 512, pImgH + (size_t)TILE_WOUT * 4608,
            pImgL + (size_t)TILE_WOUT * 4608, bout, pAtt, pPre, NN, 8, 128);
        ln_kernel<<<RG, 256>>>(pPre, ln2g, ln2b, pM);
        // GRU
        gemm_bf16<1><<<dim3(MT, 3), 256, SMB>>>(pM, 128, pImgH + (size_t)TILE_WIH * 4608,
            pImgL + (size_t)TILE_WIH * 4608, bih, nullptr, pGi, NN, 2, 384);
        gemm_bf16<1><<<dim3(MT, 3), 256, SMB>>>(pH, 128, pImgH + (size_t)TILE_WHH * 4608,
            pImgL + (size_t)TILE_WHH * 4608, bhh, nullptr, pGh, NN, 2, 384);
        gru_ln_kernel<<<RG, 256>>>(ln3g, ln3b);
    }

    copy4_kernel<<<(NN * 32 + 255) / 256, 256>>>((float4*)out, (const float4*)pX, NN * 32);
}